// round 4
// baseline (speedup 1.0000x reference)
#include <cuda_runtime.h>
#include <cstddef>

// pred_raw[b, 4h+i, 4w+j] = y[b, C[k], 4h+RO[k], 4w+CO[k]], k = 4*i+j.
// 15 unique (C,RO) rows; k=15 == k=3's y value but pairs x row 3 (handled in k=3 iter).

#define NB      2048           // 8 batches * 256 h-tiles
#define N_TOTAL 8388608.0f

__device__ float        g_partials[NB];
__device__ unsigned int g_done = 0;

// per-class packed y-row delta = (C<<20) | (RO<<10)
__device__ __forceinline__ size_t cls_delta(int k) {
    const int C[15]  = {0,3,1,4, 6,9,7,10, 1,4,8,10, 2,5,9};
    const int RO[15] = {0,0,0,0, 1,1,1,1,  2,2,3,3,  2,2,3};
    return ((size_t)C[k] << 20) | ((size_t)RO[k] << 10);
}

__global__ void __launch_bounds__(256)
loss_fused(const float* __restrict__ x, const float* __restrict__ y,
           float* __restrict__ out)
{
    const int tid  = threadIdx.x;
    const int lane = tid & 31;
    const int warp = tid >> 5;
    const int g    = blockIdx.x;
    const int b    = g >> 8;
    const int h    = g & 255;

    __shared__ float xsm[4][4][256];   // [row i][col%4 j][quad q] : 16 KB
    __shared__ float sm[8];
    __shared__ bool  s_last;

    // ---- Phase 1: stage x tile (4 rows x 1024 cols), fully coalesced ----
    {
        const size_t xbase = ((((size_t)b << 10) + (h << 2)) << 10) + (tid << 2);
        #pragma unroll
        for (int i = 0; i < 4; i++) {
            float4 v = __ldcs(reinterpret_cast<const float4*>(x + xbase + ((size_t)i << 10)));
            xsm[i][0][tid] = v.x;  xsm[i][1][tid] = v.y;
            xsm[i][2][tid] = v.z;  xsm[i][3][tid] = v.w;
        }
    }
    __syncthreads();

    // ---- Phase 2: stream 15 y class-rows as contiguous float4 loads ----
    // Warp w owns 128-col segment [128w, 128w+128); lane l -> quad q = 32w + l = tid.
    // For class k, lane loads y[C,4h+RO, 4q..4q+3] (contiguous 512 B per warp-LDG),
    // extracts component CO[k], pairs with xsm[i][j][q].
    const size_t ybase = (((size_t)(b * 12)) << 20) + (((size_t)(h << 2)) << 10)
                       + ((size_t)tid << 2);

    const int kCO[15] = {0,1,2,3, 0,1,2,3, 0,1,0,1, 2,3,2};
    float s = 0.0f;

    #pragma unroll 5
    for (int k = 0; k < 15; k++) {
        float4 v = __ldcs(reinterpret_cast<const float4*>(y + ybase + cls_delta(k)));
        float yv = (kCO[k] == 0) ? v.x : (kCO[k] == 1) ? v.y
                 : (kCO[k] == 2) ? v.z : v.w;
        const int i = k >> 2, j = k & 3;
        s += fabsf(yv - xsm[i][j][tid]);
        if (k == 3)                      // fold duplicate class 15 (i=3, j=3)
            s += fabsf(yv - xsm[3][3][tid]);
    }

    // ---- deterministic block reduction ----
    #pragma unroll
    for (int m = 16; m > 0; m >>= 1)
        s += __shfl_xor_sync(0xFFFFFFFFu, s, m);
    if (lane == 0) sm[warp] = s;
    __syncthreads();
    if (tid == 0) {
        float v = 0.0f;
        #pragma unroll
        for (int w = 0; w < 8; w++) v += sm[w];
        g_partials[g] = v;
        __threadfence();
        unsigned int prev = atomicAdd(&g_done, 1u);
        s_last = (prev == NB - 1);
    }
    __syncthreads();

    // ---- last block: fixed-order final sum (deterministic) ----
    if (s_last) {
        float t = 0.0f;
        #pragma unroll 8
        for (int idx = tid; idx < NB; idx += 256)
            t += g_partials[idx];
        #pragma unroll
        for (int m = 16; m > 0; m >>= 1)
            t += __shfl_xor_sync(0xFFFFFFFFu, t, m);
        if (lane == 0) sm[warp] = t;
        __syncthreads();
        if (tid == 0) {
            float v = 0.0f;
            #pragma unroll
            for (int w = 0; w < 8; w++) v += sm[w];
            out[0] = v * (1.0f / N_TOTAL);
            g_done = 0;                  // reset for next graph replay
        }
    }
}

extern "C" void kernel_launch(void* const* d_in, const int* in_sizes, int n_in,
                              void* d_out, int out_size) {
    const float* x;
    const float* y;
    if (in_sizes[0] == 8 * 1024 * 1024) {
        x = (const float*)d_in[0];
        y = (const float*)d_in[1];
    } else {
        x = (const float*)d_in[1];
        y = (const float*)d_in[0];
    }
    loss_fused<<<NB, 256>>>(x, y, (float*)d_out);
}

// round 5
// speedup vs baseline: 4.7090x; 4.7090x over previous
#include <cuda_runtime.h>
#include <cstddef>

// pred_raw[b, 4h+i, 4w+j] = y[b, C[k], 4h+RO[k], 4w+CO[k]], k = 4*i+j.
// k=15 duplicates k=3 exactly -> reuse in-register (15 unique y loads per 16 px).
// All class tables are indexed only with compile-time-constant k (full unroll),
// so they fold into immediate address offsets (no local memory!).

#define NB      1024           // 8 batches * 128 tile-pairs
#define N_TOTAL 8388608.0f

__device__ float        g_partials[NB];
__device__ unsigned int g_done = 0;

__global__ void __launch_bounds__(256)
loss_fused(const float* __restrict__ x, const float* __restrict__ y,
           float* __restrict__ out)
{
    const int tid  = threadIdx.x;
    const int lane = tid & 31;
    const int warp = tid >> 5;
    const int g    = blockIdx.x;
    const int b    = g >> 7;
    const int hh   = g & 127;          // tile-pair: tiles h = 2*hh, 2*hh+1

    float s = 0.0f;

    #pragma unroll
    for (int u = 0; u < 2; u++) {
        const int h = (hh << 1) + u;

        // x: 4 coalesced float4 rows of this 4x(4*256) tile
        float xs[16];
        {
            const size_t xbase = ((((size_t)b << 10) + (h << 2)) << 10) + (tid << 2);
            #pragma unroll
            for (int i = 0; i < 4; i++) {
                float4 v = *reinterpret_cast<const float4*>(x + xbase + ((size_t)i << 10));
                xs[4*i+0] = v.x; xs[4*i+1] = v.y; xs[4*i+2] = v.z; xs[4*i+3] = v.w;
            }
        }

        // y: 15 unique scalar loads, constant-folded offsets
        const int kC[16]  = {0,3,1,4, 6,9,7,10, 1,4,8,10, 2,5,9,4};
        const int kRO[16] = {0,0,0,0, 1,1,1,1,  2,2,3,3,  2,2,3,0};
        const int kCO[16] = {0,1,2,3, 0,1,2,3,  0,1,0,1,  2,3,2,3};

        float yv[16];
        const size_t ybase = (((size_t)(b * 12)) << 20)
                           + (((size_t)(h << 2)) << 10) + (tid << 2);
        #pragma unroll
        for (int k = 0; k < 15; k++)
            yv[k] = y[ybase + ((size_t)kC[k] << 20) + ((size_t)kRO[k] << 10) + kCO[k]];
        yv[15] = yv[3];

        #pragma unroll
        for (int k = 0; k < 16; k++)
            s += fabsf(yv[k] - xs[k]);
    }

    // ---- deterministic block reduction ----
    #pragma unroll
    for (int m = 16; m > 0; m >>= 1)
        s += __shfl_xor_sync(0xFFFFFFFFu, s, m);

    __shared__ float sm[8];
    __shared__ bool  s_last;
    if (lane == 0) sm[warp] = s;
    __syncthreads();
    if (tid == 0) {
        float v = 0.0f;
        #pragma unroll
        for (int w = 0; w < 8; w++) v += sm[w];
        g_partials[g] = v;
        __threadfence();
        unsigned int prev = atomicAdd(&g_done, 1u);
        s_last = (prev == NB - 1);
    }
    __syncthreads();

    // ---- last block: fixed-order final sum (deterministic) ----
    if (s_last) {
        float t = 0.0f;
        #pragma unroll 4
        for (int idx = tid; idx < NB; idx += 256)
            t += g_partials[idx];
        #pragma unroll
        for (int m = 16; m > 0; m >>= 1)
            t += __shfl_xor_sync(0xFFFFFFFFu, t, m);
        if (lane == 0) sm[warp] = t;
        __syncthreads();
        if (tid == 0) {
            float v = 0.0f;
            #pragma unroll
            for (int w = 0; w < 8; w++) v += sm[w];
            out[0] = v * (1.0f / N_TOTAL);
            g_done = 0;                  // reset for next graph replay
        }
    }
}

extern "C" void kernel_launch(void* const* d_in, const int* in_sizes, int n_in,
                              void* d_out, int out_size) {
    const float* x;
    const float* y;
    if (in_sizes[0] == 8 * 1024 * 1024) {
        x = (const float*)d_in[0];
        y = (const float*)d_in[1];
    } else {
        x = (const float*)d_in[1];
        y = (const float*)d_in[0];
    }
    loss_fused<<<NB, 256>>>(x, y, (float*)d_out);
}